// round 3
// baseline (speedup 1.0000x reference)
#include <cuda_runtime.h>
#include <math.h>

#define Bq  32
#define Sq  256
#define Tq  32
#define TQn 31
#define Vq  32000
#define Eq  128
#define Hq  256
#define HDq 512

// ---------------- scratch (device globals; no allocation) ----------------
__device__ float d_X[Sq*Bq*2*Eq];          // [s*B+b, 256] encoder input (embed||marker)
__device__ float d_xprojF[Sq*Bq*4*Hq];     // [s*B+b, 1024]  x@Wf_ih^T + bf
__device__ float d_xprojB[Sq*Bq*4*Hq];     // [s*B+b, 1024]  x@Wb_ih^T + bb
__device__ float d_ENC[Sq*Bq*2*Hq];        // [s*B+b, 512] enc_out (fwd||bwd)
__device__ float d_encproj[Sq*Bq*Hq];      // [s*B+b, 256]
__device__ float d_hT[2][2][Hq*Bq];        // [dir][parity][unit*32+b]
__device__ float d_cT[2][Hq*Bq];
__device__ float d_hdT[2][HDq*Bq];         // decoder h [parity][unit*32+b]
__device__ float d_cdT[HDq*Bq];
__device__ float d_qxT[TQn*Eq*Bq];         // [t][k][b]
__device__ float d_Wcomb[4*HDq*HDq];       // Wd_ih[:,128:] + Wd_hh
__device__ float d_Z[TQn*Bq*2*HDq];        // [(b*31+t), 1024] = [h | ctx]

__device__ __forceinline__ float sigm(float x){ return 1.0f/(1.0f+expf(-x)); }
__device__ __forceinline__ float tanh_(float x){ return 1.0f - 2.0f/(expf(2.0f*x)+1.0f); }

// ---------------- setup: embeddings, Wcomb, zero states ----------------
__global__ void k_setup(const int* __restrict__ ctx, const int* __restrict__ mark,
                        const int* __restrict__ qid,
                        const float* __restrict__ embed, const float* __restrict__ membed,
                        const float* __restrict__ Wd_ih, const float* __restrict__ Wd_hh)
{
    const int NX = Sq*Bq*256;
    const int NQ = TQn*Eq*Bq;
    const int NW = 4*HDq*HDq;
    const int NH = 2*2*Hq*Bq;      // d_hT
    const int NC = 2*Hq*Bq;        // d_cT
    const int total = NX + NQ + NW + NH + NC;
    for (int idx = blockIdx.x*blockDim.x + threadIdx.x; idx < total; idx += gridDim.x*blockDim.x){
        if (idx < NX){
            int row = idx >> 8; int k = idx & 255;
            int s = row >> 5, b = row & 31;
            float v;
            if (k < Eq) v = embed[(size_t)ctx[b*Sq+s]*Eq + k];
            else        v = membed[(size_t)mark[b*Sq+s]*Eq + (k-Eq)];
            d_X[idx] = v;
        } else if (idx < NX+NQ){
            int i = idx - NX;
            int t = i/(Eq*Bq); int r = i%(Eq*Bq); int k = r >> 5; int b = r & 31;
            d_qxT[i] = embed[(size_t)qid[b*Tq+t]*Eq + k];
        } else if (idx < NX+NQ+NW){
            int i = idx - NX - NQ; int j = i >> 9; int k = i & 511;
            d_Wcomb[i] = Wd_ih[(size_t)j*640 + 128 + k] + Wd_hh[(size_t)j*512 + k];
        } else {
            int i = idx - NX - NQ - NW;
            if (i < NH) ((float*)d_hT)[i] = 0.0f;
            else        ((float*)d_cT)[i-NH] = 0.0f;
        }
    }
}

// ---------------- generic fp32 GEMM: C[M,N] = A[M,K] * B[N,K]^T + bias ----------------
#define GBM 128
#define GBN 64
#define GBK 16
__global__ void __launch_bounds__(256)
k_gemm(const float* __restrict__ A, int lda,
       const float* __restrict__ Bw, int ldb,
       const float* __restrict__ bias,
       float* __restrict__ C, int ldc,
       int M, int N, int K)
{
    __shared__ float As[GBK][GBM+4];
    __shared__ float Bs[GBK][GBN+4];
    int tid = threadIdx.x;
    int tx = tid & 15, ty = tid >> 4;
    int m0 = blockIdx.y * GBM, n0 = blockIdx.x * GBN;

    float acc[8][4];
    #pragma unroll
    for (int i=0;i<8;i++){ acc[i][0]=0.f;acc[i][1]=0.f;acc[i][2]=0.f;acc[i][3]=0.f; }

    int arow = tid >> 1;           // 0..127
    int ak   = (tid & 1) * 8;      // 0 / 8
    int brow = tid >> 2;           // 0..63
    int bk   = (tid & 3) * 4;      // 0/4/8/12

    for (int k0 = 0; k0 < K; k0 += GBK){
        // A tile
        {
            int gm = m0 + arow;
            float4 v0, v1;
            if (gm < M){
                const float* src = A + (size_t)gm*lda + k0 + ak;
                v0 = *(const float4*)src;
                v1 = *(const float4*)(src+4);
            } else {
                v0 = make_float4(0,0,0,0); v1 = v0;
            }
            As[ak+0][arow]=v0.x; As[ak+1][arow]=v0.y; As[ak+2][arow]=v0.z; As[ak+3][arow]=v0.w;
            As[ak+4][arow]=v1.x; As[ak+5][arow]=v1.y; As[ak+6][arow]=v1.z; As[ak+7][arow]=v1.w;
        }
        // B tile (N is always a multiple of GBN here)
        {
            int gn = n0 + brow;
            float4 v = *(const float4*)(Bw + (size_t)gn*ldb + k0 + bk);
            Bs[bk+0][brow]=v.x; Bs[bk+1][brow]=v.y; Bs[bk+2][brow]=v.z; Bs[bk+3][brow]=v.w;
        }
        __syncthreads();
        #pragma unroll
        for (int kk = 0; kk < GBK; kk++){
            float4 b4 = *(const float4*)&Bs[kk][tx*4];
            float4 a0 = *(const float4*)&As[kk][ty*8];
            float4 a1 = *(const float4*)&As[kk][ty*8+4];
            float av[8] = {a0.x,a0.y,a0.z,a0.w,a1.x,a1.y,a1.z,a1.w};
            float bv[4] = {b4.x,b4.y,b4.z,b4.w};
            #pragma unroll
            for (int i=0;i<8;i++){
                #pragma unroll
                for (int j=0;j<4;j++) acc[i][j] = fmaf(av[i], bv[j], acc[i][j]);
            }
        }
        __syncthreads();
    }

    float4 bb = make_float4(0,0,0,0);
    if (bias) bb = *(const float4*)(bias + n0 + tx*4);
    #pragma unroll
    for (int i=0;i<8;i++){
        int gm = m0 + ty*8 + i;
        if (gm < M){
            float4 o;
            o.x = acc[i][0]+bb.x; o.y = acc[i][1]+bb.y;
            o.z = acc[i][2]+bb.z; o.w = acc[i][3]+bb.w;
            *(float4*)(C + (size_t)gm*ldc + n0 + tx*4) = o;
        }
    }
}

// ---------------- encoder scan step (both directions) ----------------
__global__ void __launch_bounds__(256)
k_enc_step(int t, const float* __restrict__ Wf_hh, const float* __restrict__ Wb_hh)
{
    int dir = blockIdx.x >> 5;
    int b   = threadIdx.x & 31;
    int jj  = ((blockIdx.x & 31) << 3) + (threadIdx.x >> 5);   // 0..255
    int s   = dir ? (Sq-1-t) : t;
    const float* __restrict__ xp  = dir ? d_xprojB : d_xprojF;
    const float* __restrict__ Whh = dir ? Wb_hh : Wf_hh;
    int rp = t & 1;
    const float* __restrict__ h = d_hT[dir][rp];

    const float* base = xp + (size_t)(s*Bq+b)*1024 + jj;
    float a0 = base[0], a1 = base[256], a2 = base[512], a3 = base[768];

    const float* w0 = Whh + (size_t)jj*Hq;
    const float* w1 = w0 + 256*Hq;
    const float* w2 = w1 + 256*Hq;
    const float* w3 = w2 + 256*Hq;
    #pragma unroll 4
    for (int k = 0; k < Hq; k += 4){
        float4 v0 = *(const float4*)(w0+k);
        float4 v1 = *(const float4*)(w1+k);
        float4 v2 = *(const float4*)(w2+k);
        float4 v3 = *(const float4*)(w3+k);
        float h0 = h[(k+0)*32+b], h1 = h[(k+1)*32+b];
        float h2 = h[(k+2)*32+b], h3 = h[(k+3)*32+b];
        a0 += h0*v0.x + h1*v0.y + h2*v0.z + h3*v0.w;
        a1 += h0*v1.x + h1*v1.y + h2*v1.z + h3*v1.w;
        a2 += h0*v2.x + h1*v2.y + h2*v2.z + h3*v2.w;
        a3 += h0*v3.x + h1*v3.y + h2*v3.z + h3*v3.w;
    }
    int idx = jj*32 + b;
    float co = d_cT[dir][idx];
    float cn = sigm(a1)*co + sigm(a0)*tanh_(a2);
    float hn = sigm(a3)*tanh_(cn);
    d_cT[dir][idx] = cn;
    d_hT[dir][rp^1][idx] = hn;
    d_ENC[(size_t)(s*Bq+b)*(2*Hq) + dir*Hq + jj] = hn;
}

// ---------------- decoder init from encoder finals (parity 0 after 256 steps) ----------------
__global__ void k_dec_init()
{
    int idx = blockIdx.x*blockDim.x + threadIdx.x;
    if (idx >= HDq*Bq) return;
    int k = idx >> 5, b = idx & 31;
    float hv, cv;
    if (k < Hq){ hv = d_hT[0][0][k*32+b];       cv = d_cT[0][k*32+b]; }
    else       { hv = d_hT[1][0][(k-Hq)*32+b];  cv = d_cT[1][(k-Hq)*32+b]; }
    d_hdT[0][idx] = hv;
    d_cdT[idx]    = cv;
}

// ---------------- decoder LSTM step ----------------
__global__ void __launch_bounds__(256)
k_dec_step(int t, const float* __restrict__ Wd_ih, const float* __restrict__ bd)
{
    int b  = threadIdx.x & 31;
    int jj = (blockIdx.x << 3) + (threadIdx.x >> 5);   // 0..511
    int rp = t & 1;
    float a0 = bd[jj], a1 = bd[512+jj], a2 = bd[1024+jj], a3 = bd[1536+jj];

    const float* __restrict__ qx = d_qxT + (size_t)t*Eq*Bq;
    const float* wi0 = Wd_ih + (size_t)jj*640;
    const float* wi1 = wi0 + (size_t)512*640;
    const float* wi2 = wi1 + (size_t)512*640;
    const float* wi3 = wi2 + (size_t)512*640;
    #pragma unroll 4
    for (int k = 0; k < Eq; k += 4){
        float4 v0 = *(const float4*)(wi0+k);
        float4 v1 = *(const float4*)(wi1+k);
        float4 v2 = *(const float4*)(wi2+k);
        float4 v3 = *(const float4*)(wi3+k);
        float x0 = qx[(k+0)*32+b], x1 = qx[(k+1)*32+b];
        float x2 = qx[(k+2)*32+b], x3 = qx[(k+3)*32+b];
        a0 += x0*v0.x + x1*v0.y + x2*v0.z + x3*v0.w;
        a1 += x0*v1.x + x1*v1.y + x2*v1.z + x3*v1.w;
        a2 += x0*v2.x + x1*v2.y + x2*v2.z + x3*v2.w;
        a3 += x0*v3.x + x1*v3.y + x2*v3.z + x3*v3.w;
    }
    const float* __restrict__ h = d_hdT[rp];
    const float* wc0 = d_Wcomb + (size_t)jj*512;
    const float* wc1 = wc0 + (size_t)512*512;
    const float* wc2 = wc1 + (size_t)512*512;
    const float* wc3 = wc2 + (size_t)512*512;
    #pragma unroll 4
    for (int k = 0; k < HDq; k += 4){
        float4 v0 = *(const float4*)(wc0+k);
        float4 v1 = *(const float4*)(wc1+k);
        float4 v2 = *(const float4*)(wc2+k);
        float4 v3 = *(const float4*)(wc3+k);
        float h0 = h[(k+0)*32+b], h1 = h[(k+1)*32+b];
        float h2 = h[(k+2)*32+b], h3 = h[(k+3)*32+b];
        a0 += h0*v0.x + h1*v0.y + h2*v0.z + h3*v0.w;
        a1 += h0*v1.x + h1*v1.y + h2*v1.z + h3*v1.w;
        a2 += h0*v2.x + h1*v2.y + h2*v2.z + h3*v2.w;
        a3 += h0*v3.x + h1*v3.y + h2*v3.z + h3*v3.w;
    }
    int idx = jj*32 + b;
    float co = d_cdT[idx];
    float cn = sigm(a1)*co + sigm(a0)*tanh_(a2);
    float hn = sigm(a3)*tanh_(cn);
    d_cdT[idx] = cn;
    d_hdT[rp^1][idx] = hn;
    d_Z[(size_t)(b*TQn + t)*1024 + jj] = hn;
}

// ---------------- attention: h_part, scores, softmax, context ----------------
__global__ void __launch_bounds__(256)
k_attn(int t, const float* __restrict__ A1_w, const float* __restrict__ A1_b,
       const float* __restrict__ A2_w, const float* __restrict__ A2_b,
       const int* __restrict__ mask)
{
    __shared__ float hp[256];
    __shared__ float sc[256];
    __shared__ float red[32];
    int b = blockIdx.x;
    int tid = threadIdx.x;
    int wp = (t+1) & 1;

    // h_part[m] = A1_b[m] + sum_k h_new[k]*A1_w[m, k]   (k < 512)
    {
        const float* __restrict__ h = d_hdT[wp];
        const float* w = A1_w + (size_t)tid*1024;
        float acc = A1_b[tid];
        #pragma unroll 4
        for (int k = 0; k < HDq; k += 4){
            float4 v = *(const float4*)(w+k);
            acc += h[(k+0)*32+b]*v.x + h[(k+1)*32+b]*v.y
                 + h[(k+2)*32+b]*v.z + h[(k+3)*32+b]*v.w;
        }
        hp[tid] = acc;
    }
    __syncthreads();

    // scores[s]
    {
        int s = tid;
        const float* ep = d_encproj + (size_t)(s*Bq+b)*256;
        float a = A2_b[0];
        #pragma unroll 4
        for (int m = 0; m < 256; m++)
            a += tanh_(hp[m] + ep[m]) * A2_w[m];
        a += (1.0f - (float)mask[b*Sq+s]) * (-1e30f);
        sc[tid] = a;
    }
    __syncthreads();

    // softmax over 256
    float v = sc[tid];
    #pragma unroll
    for (int o=16;o;o>>=1) v = fmaxf(v, __shfl_xor_sync(0xffffffffu, v, o));
    if ((tid & 31) == 0) red[tid>>5] = v;
    __syncthreads();
    if (tid == 0){ float m = red[0]; for (int i=1;i<8;i++) m = fmaxf(m, red[i]); red[16] = m; }
    __syncthreads();
    float mx = red[16];
    float e = expf(sc[tid] - mx);
    float s2 = e;
    #pragma unroll
    for (int o=16;o;o>>=1) s2 += __shfl_xor_sync(0xffffffffu, s2, o);
    if ((tid & 31) == 0) red[8 + (tid>>5)] = s2;
    __syncthreads();
    if (tid == 0){ float ss = 0.f; for (int i=0;i<8;i++) ss += red[8+i]; red[17] = 1.0f/ss; }
    __syncthreads();
    sc[tid] = e * red[17];
    __syncthreads();

    // ctx[d] = sum_s attn[s] * ENC[(s,b), d]
    float* z = d_Z + (size_t)(b*TQn + t)*1024 + 512;
    for (int d = tid; d < 512; d += 256){
        const float* eb = d_ENC + (size_t)b*512 + d;
        float acc = 0.f;
        #pragma unroll 4
        for (int s = 0; s < Sq; s++)
            acc += sc[s] * eb[(size_t)s*Bq*512];
        z[d] = acc;
    }
}

// ---------------- host launch ----------------
static void* symaddr(const void* sym){
    void* p = nullptr;
    cudaGetSymbolAddress(&p, sym);
    return p;
}

extern "C" void kernel_launch(void* const* d_in, const int* in_sizes, int n_in,
                              void* d_out, int out_size)
{
    const int*   ctx    = (const int*)  d_in[0];
    const int*   mark   = (const int*)  d_in[1];
    const int*   qid    = (const int*)  d_in[2];
    const int*   mask   = (const int*)  d_in[3];
    const float* embed  = (const float*)d_in[4];
    const float* membed = (const float*)d_in[5];
    const float* Wf_ih  = (const float*)d_in[6];
    const float* Wf_hh  = (const float*)d_in[7];
    const float* bf     = (const float*)d_in[8];
    const float* Wb_ih  = (const float*)d_in[9];
    const float* Wb_hh  = (const float*)d_in[10];
    const float* bb     = (const float*)d_in[11];
    const float* Wd_ih  = (const float*)d_in[12];
    const float* Wd_hh  = (const float*)d_in[13];
    const float* bd     = (const float*)d_in[14];
    const float* A1_w   = (const float*)d_in[15];
    const float* A1_b   = (const float*)d_in[16];
    const float* A2_w   = (const float*)d_in[17];
    const float* A2_b   = (const float*)d_in[18];
    const float* O_w    = (const float*)d_in[19];
    const float* O_b    = (const float*)d_in[20];
    float* out = (float*)d_out;

    float* pX    = (float*)symaddr(d_X);
    float* pxF   = (float*)symaddr(d_xprojF);
    float* pxB   = (float*)symaddr(d_xprojB);
    float* pENC  = (float*)symaddr(d_ENC);
    float* pproj = (float*)symaddr(d_encproj);
    float* pZ    = (float*)symaddr(d_Z);

    // 1. embeddings + Wcomb + zero states
    k_setup<<<2048, 256>>>(ctx, mark, qid, embed, membed, Wd_ih, Wd_hh);

    // 2. x-projections for both directions (bias folded in)
    k_gemm<<<dim3(1024/GBN, (Sq*Bq)/GBM), 256>>>(pX, 256, Wf_ih, 256, bf, pxF, 1024, Sq*Bq, 1024, 256);
    k_gemm<<<dim3(1024/GBN, (Sq*Bq)/GBM), 256>>>(pX, 256, Wb_ih, 256, bb, pxB, 1024, Sq*Bq, 1024, 256);

    // 3. encoder recurrence (fwd + bwd in the same launch)
    for (int t = 0; t < Sq; t++)
        k_enc_step<<<64, 256>>>(t, Wf_hh, Wb_hh);

    // 4. decoder init + encoder-side attention projection
    k_dec_init<<<64, 256>>>();
    k_gemm<<<dim3(256/GBN, (Sq*Bq)/GBM), 256>>>(pENC, 512, A1_w + 512, 1024, nullptr, pproj, 256, Sq*Bq, 256, 512);

    // 5. decoder steps
    for (int t = 0; t < TQn; t++){
        k_dec_step<<<64, 256>>>(t, Wd_ih, bd);
        k_attn<<<32, 256>>>(t, A1_w, A1_b, A2_w, A2_b, mask);
    }

    // 6. big output projection straight into d_out ([b*31+t] rows == [B,T-1,V])
    k_gemm<<<dim3(Vq/GBN, (TQn*Bq + GBM - 1)/GBM), 256>>>(pZ, 1024, O_w, 1024, O_b, out, Vq, TQn*Bq, Vq, 1024);

    (void)in_sizes; (void)n_in; (void)out_size;
}

// round 4
// speedup vs baseline: 2.5631x; 2.5631x over previous
#include <cuda_runtime.h>
#include <math.h>

#define Bq  32
#define Sq  256
#define Tq  32
#define TQn 31
#define Vq  32000
#define Eq  128
#define Hq  256
#define HDq 512

// ---------------- scratch (device globals; no allocation) ----------------
__device__ float d_X[Sq*Bq*2*Eq];          // [s*B+b, 256] encoder input (embed||marker)
__device__ float d_xprojF[Sq*Bq*4*Hq];     // [s*B+b, 1024]  x@Wf_ih^T + bf
__device__ float d_xprojB[Sq*Bq*4*Hq];     // [s*B+b, 1024]  x@Wb_ih^T + bb
__device__ float d_ENC[Sq*Bq*2*Hq];        // [s*B+b, 512] enc_out (fwd||bwd)
__device__ float d_encproj[Sq*Bq*Hq];      // [s*B+b, 256]
__device__ float d_hT[2][2][Hq*Bq];        // [dir][parity][unit*32+b]
__device__ float d_cT[2][Hq*Bq];           // final encoder c
__device__ float d_hdT[2][HDq*Bq];         // decoder h [parity][unit*32+b]
__device__ float d_qxT[TQn*Eq*Bq];         // [t][k][b]
__device__ float d_Wcomb[4*HDq*HDq];       // Wd_ih[:,128:] + Wd_hh
__device__ float d_Z[TQn*Bq*2*HDq];        // [(b*31+t), 1024] = [h | ctx]
__device__ float d_hp[Bq*Hq];              // attention h_part [b*256+m]
__device__ float d_scoresG[Bq*Sq];         // attention raw scores [b*256+s]

__device__ unsigned g_bar_cnt = 0;
__device__ unsigned g_bar_gen = 0;

__device__ __forceinline__ float sigm(float x){ return 1.0f/(1.0f+expf(-x)); }
__device__ __forceinline__ float tanh_(float x){ return 1.0f - 2.0f/(expf(2.0f*x)+1.0f); }
__device__ __forceinline__ float tanha(float x){ float y; asm("tanh.approx.f32 %0, %1;" : "=f"(y) : "f"(x)); return y; }

// grid-wide barrier: all blocks co-resident (grid <= 148), generation-based.
__device__ __forceinline__ void grid_bar(unsigned nb){
    __syncthreads();
    if (threadIdx.x == 0){
        unsigned gen = *((volatile unsigned*)&g_bar_gen);
        __threadfence();   // release prior writes; also orders gen read before arrive
        unsigned ticket = atomicAdd(&g_bar_cnt, 1);
        if (ticket == nb - 1){
            g_bar_cnt = 0;
            __threadfence();
            atomicAdd(&g_bar_gen, 1);
        } else {
            while (*((volatile unsigned*)&g_bar_gen) == gen) {}
        }
    }
    __syncthreads();
}

// ---------------- setup: embeddings, Wcomb ----------------
__global__ void k_setup(const int* __restrict__ ctx, const int* __restrict__ mark,
                        const int* __restrict__ qid,
                        const float* __restrict__ embed, const float* __restrict__ membed,
                        const float* __restrict__ Wd_ih, const float* __restrict__ Wd_hh)
{
    const int NX = Sq*Bq*256;
    const int NQ = TQn*Eq*Bq;
    const int NW = 4*HDq*HDq;
    const int total = NX + NQ + NW;
    for (int idx = blockIdx.x*blockDim.x + threadIdx.x; idx < total; idx += gridDim.x*blockDim.x){
        if (idx < NX){
            int row = idx >> 8; int k = idx & 255;
            int s = row >> 5, b = row & 31;
            float v;
            if (k < Eq) v = embed[(size_t)ctx[b*Sq+s]*Eq + k];
            else        v = membed[(size_t)mark[b*Sq+s]*Eq + (k-Eq)];
            d_X[idx] = v;
        } else if (idx < NX+NQ){
            int i = idx - NX;
            int t = i/(Eq*Bq); int r = i%(Eq*Bq); int k = r >> 5; int b = r & 31;
            d_qxT[i] = embed[(size_t)qid[b*Tq+t]*Eq + k];
        } else {
            int i = idx - NX - NQ; int j = i >> 9; int k = i & 511;
            d_Wcomb[i] = Wd_ih[(size_t)j*640 + 128 + k] + Wd_hh[(size_t)j*512 + k];
        }
    }
}

// ---------------- generic fp32 GEMM: C[M,N] = A[M,K] * B[N,K]^T + bias ----------------
#define GBM 128
#define GBN 64
#define GBK 16
__global__ void __launch_bounds__(256)
k_gemm(const float* __restrict__ A, int lda,
       const float* __restrict__ Bw, int ldb,
       const float* __restrict__ bias,
       float* __restrict__ C, int ldc,
       int M, int N, int K)
{
    __shared__ float As[GBK][GBM+4];
    __shared__ float Bs[GBK][GBN+4];
    int tid = threadIdx.x;
    int tx = tid & 15, ty = tid >> 4;
    int m0 = blockIdx.y * GBM, n0 = blockIdx.x * GBN;

    float acc[8][4];
    #pragma unroll
    for (int i=0;i<8;i++){ acc[i][0]=0.f;acc[i][1]=0.f;acc[i][2]=0.f;acc[i][3]=0.f; }

    int arow = tid >> 1;
    int ak   = (tid & 1) * 8;
    int brow = tid >> 2;
    int bk   = (tid & 3) * 4;

    for (int k0 = 0; k0 < K; k0 += GBK){
        {
            int gm = m0 + arow;
            float4 v0, v1;
            if (gm < M){
                const float* src = A + (size_t)gm*lda + k0 + ak;
                v0 = *(const float4*)src;
                v1 = *(const float4*)(src+4);
            } else {
                v0 = make_float4(0,0,0,0); v1 = v0;
            }
            As[ak+0][arow]=v0.x; As[ak+1][arow]=v0.y; As[ak+2][arow]=v0.z; As[ak+3][arow]=v0.w;
            As[ak+4][arow]=v1.x; As[ak+5][arow]=v1.y; As[ak+6][arow]=v1.z; As[ak+7][arow]=v1.w;
        }
        {
            int gn = n0 + brow;
            float4 v = *(const float4*)(Bw + (size_t)gn*ldb + k0 + bk);
            Bs[bk+0][brow]=v.x; Bs[bk+1][brow]=v.y; Bs[bk+2][brow]=v.z; Bs[bk+3][brow]=v.w;
        }
        __syncthreads();
        #pragma unroll
        for (int kk = 0; kk < GBK; kk++){
            float4 b4 = *(const float4*)&Bs[kk][tx*4];
            float4 a0 = *(const float4*)&As[kk][ty*8];
            float4 a1 = *(const float4*)&As[kk][ty*8+4];
            float av[8] = {a0.x,a0.y,a0.z,a0.w,a1.x,a1.y,a1.z,a1.w};
            float bv[4] = {b4.x,b4.y,b4.z,b4.w};
            #pragma unroll
            for (int i=0;i<8;i++){
                #pragma unroll
                for (int j=0;j<4;j++) acc[i][j] = fmaf(av[i], bv[j], acc[i][j]);
            }
        }
        __syncthreads();
    }

    float4 bb = make_float4(0,0,0,0);
    if (bias) bb = *(const float4*)(bias + n0 + tx*4);
    #pragma unroll
    for (int i=0;i<8;i++){
        int gm = m0 + ty*8 + i;
        if (gm < M){
            float4 o;
            o.x = acc[i][0]+bb.x; o.y = acc[i][1]+bb.y;
            o.z = acc[i][2]+bb.z; o.w = acc[i][3]+bb.w;
            *(float4*)(C + (size_t)gm*ldc + n0 + tx*4) = o;
        }
    }
}

// ---------------- persistent encoder: 128 blocks x 128 threads ----------------
#define ENC_BLOCKS 128
// dyn smem: ws 4096 floats (16KB) + hs 8192 floats (32KB) = 49152 bytes
__global__ void __launch_bounds__(128)
k_enc_persist(const float* __restrict__ Wf_hh, const float* __restrict__ Wb_hh)
{
    extern __shared__ float sm[];
    float* ws = sm;            // [lj][gate][k]  (4*4*256)
    float* hs = sm + 4096;     // [k*32+b]       (256*32)

    int blk  = blockIdx.x;
    int dir  = blk >> 6;
    int ublk = blk & 63;
    int tid  = threadIdx.x;
    int lj   = tid >> 5;
    int b    = tid & 31;
    int jj   = ublk*4 + lj;
    const float* __restrict__ Whh = dir ? Wb_hh : Wf_hh;
    const float* __restrict__ xp  = dir ? d_xprojB : d_xprojF;

    // load weight slice to smem (once)
    for (int f = tid*4; f < 4096; f += 512){
        int l = f >> 10; int g = (f >> 8) & 3; int k = f & 255;
        int row = g*256 + ublk*4 + l;
        *(float4*)(ws + f) = *(const float4*)(Whh + (size_t)row*256 + k);
    }
    // zero initial h (parity 0)
    d_hT[dir][0][jj*32 + b] = 0.0f;
    float c = 0.0f;

    const float* w0 = ws + (lj*4+0)*256;
    const float* w1 = ws + (lj*4+1)*256;
    const float* w2 = ws + (lj*4+2)*256;
    const float* w3 = ws + (lj*4+3)*256;

    for (int t = 0; t < Sq; t++){
        grid_bar(ENC_BLOCKS);
        // stage h (cross-block state -> ldcg)
        const float* hg = d_hT[dir][t & 1];
        for (int i = tid*4; i < 8192; i += 512)
            *(float4*)(hs + i) = __ldcg((const float4*)(hg + i));
        __syncthreads();

        int s = dir ? (255 - t) : t;
        const float* base = xp + (size_t)(s*32 + b)*1024 + jj;
        float a0 = base[0], a1 = base[256], a2 = base[512], a3 = base[768];
        #pragma unroll 4
        for (int k = 0; k < 256; k += 4){
            float4 v0 = *(const float4*)(w0 + k);
            float4 v1 = *(const float4*)(w1 + k);
            float4 v2 = *(const float4*)(w2 + k);
            float4 v3 = *(const float4*)(w3 + k);
            float h0 = hs[(k+0)*32+b], h1 = hs[(k+1)*32+b];
            float h2 = hs[(k+2)*32+b], h3 = hs[(k+3)*32+b];
            a0 += h0*v0.x + h1*v0.y + h2*v0.z + h3*v0.w;
            a1 += h0*v1.x + h1*v1.y + h2*v1.z + h3*v1.w;
            a2 += h0*v2.x + h1*v2.y + h2*v2.z + h3*v2.w;
            a3 += h0*v3.x + h1*v3.y + h2*v3.z + h3*v3.w;
        }
        float cn = sigm(a1)*c + sigm(a0)*tanh_(a2);
        float hn = sigm(a3)*tanh_(cn);
        c = cn;
        d_hT[dir][(t&1)^1][jj*32+b] = hn;
        d_ENC[(size_t)(s*32+b)*512 + dir*256 + jj] = hn;
    }
    d_cT[dir][jj*32+b] = c;   // final c for decoder init
}

// ---------------- persistent decoder: 128 blocks x 128 threads ----------------
#define DEC_BLOCKS 128
// dyn smem: wd 10240 (40KB) + hs 16384 (64KB) + scr 4096 (16KB) = 122880 bytes
__global__ void __launch_bounds__(128)
k_dec_persist(const float* __restrict__ Wd_ih, const float* __restrict__ bd,
              const float* __restrict__ A1_w,  const float* __restrict__ A1_b,
              const float* __restrict__ A2_w,  const float* __restrict__ A2_b,
              const int*   __restrict__ mask)
{
    extern __shared__ float sm[];
    float* wd  = sm;               // [lj][gate][k0..639]
    float* hs  = sm + 10240;       // [k*32+b]  (512*32)
    float* scr = sm + 10240 + 16384; // 4096 floats scratch (qx / hp / scores / red)

    int blk = blockIdx.x;
    int tid = threadIdx.x;
    int lj  = tid >> 5;
    int b   = tid & 31;
    int jj  = blk*4 + lj;          // 0..511

    // load weight slice (once): k<128 from Wd_ih (x part), k>=128 from Wcomb
    for (int f = tid*4; f < 10240; f += 512){
        int l = f / 2560; int r = f % 2560; int g = r / 640; int k = r % 640;
        int row = g*512 + blk*4 + l;
        float4 v;
        if (k < 128) v = *(const float4*)(Wd_ih  + (size_t)row*640 + k);
        else         v = *(const float4*)(d_Wcomb + (size_t)row*512 + (k-128));
        *(float4*)(wd + f) = v;
    }

    // decoder init from encoder finals
    float c;
    {
        float hv;
        if (jj < Hq){ hv = d_hT[0][0][jj*32+b];       c = d_cT[0][jj*32+b]; }
        else        { hv = d_hT[1][0][(jj-Hq)*32+b];  c = d_cT[1][(jj-Hq)*32+b]; }
        d_hdT[0][jj*32+b] = hv;
    }

    const float* w0 = wd + (lj*4+0)*640;
    const float* w1 = wd + (lj*4+1)*640;
    const float* w2 = wd + (lj*4+2)*640;
    const float* w3 = wd + (lj*4+3)*640;
    float bd0 = bd[jj], bd1 = bd[512+jj], bd2 = bd[1024+jj], bd3 = bd[1536+jj];

    for (int t = 0; t < TQn; t++){
        grid_bar(DEC_BLOCKS);
        // ---- stage h_prev (64KB) + qx(t) (16KB) ----
        {
            const float* hg = d_hdT[t & 1];
            for (int i = tid*4; i < 16384; i += 512)
                *(float4*)(hs + i) = __ldcg((const float4*)(hg + i));
            const float* qg = d_qxT + (size_t)t*Eq*Bq;
            for (int i = tid*4; i < 4096; i += 512)
                *(float4*)(scr + i) = *(const float4*)(qg + i);   // read-only input
        }
        __syncthreads();

        // ---- Phase A: LSTM gates ----
        {
            float a0 = bd0, a1 = bd1, a2 = bd2, a3 = bd3;
            #pragma unroll 4
            for (int k = 0; k < 128; k += 4){
                float4 v0 = *(const float4*)(w0 + k);
                float4 v1 = *(const float4*)(w1 + k);
                float4 v2 = *(const float4*)(w2 + k);
                float4 v3 = *(const float4*)(w3 + k);
                float x0 = scr[(k+0)*32+b], x1 = scr[(k+1)*32+b];
                float x2 = scr[(k+2)*32+b], x3 = scr[(k+3)*32+b];
                a0 += x0*v0.x + x1*v0.y + x2*v0.z + x3*v0.w;
                a1 += x0*v1.x + x1*v1.y + x2*v1.z + x3*v1.w;
                a2 += x0*v2.x + x1*v2.y + x2*v2.z + x3*v2.w;
                a3 += x0*v3.x + x1*v3.y + x2*v3.z + x3*v3.w;
            }
            #pragma unroll 4
            for (int k = 0; k < 512; k += 4){
                float4 v0 = *(const float4*)(w0 + 128 + k);
                float4 v1 = *(const float4*)(w1 + 128 + k);
                float4 v2 = *(const float4*)(w2 + 128 + k);
                float4 v3 = *(const float4*)(w3 + 128 + k);
                float h0 = hs[(k+0)*32+b], h1 = hs[(k+1)*32+b];
                float h2 = hs[(k+2)*32+b], h3 = hs[(k+3)*32+b];
                a0 += h0*v0.x + h1*v0.y + h2*v0.z + h3*v0.w;
                a1 += h0*v1.x + h1*v1.y + h2*v1.z + h3*v1.w;
                a2 += h0*v2.x + h1*v2.y + h2*v2.z + h3*v2.w;
                a3 += h0*v3.x + h1*v3.y + h2*v3.z + h3*v3.w;
            }
            float cn = sigm(a1)*c + sigm(a0)*tanh_(a2);
            float hn = sigm(a3)*tanh_(cn);
            c = cn;
            d_hdT[(t&1)^1][jj*32+b] = hn;
            d_Z[((size_t)b*TQn + t)*1024 + jj] = hn;
        }
        grid_bar(DEC_BLOCKS);

        // ---- Phase B: hp[b][m] = A1_b[m] + h_new[:,b] . A1_w[m,:512] ----
        {
            // stage h_new
            const float* hg = d_hdT[(t&1)^1];
            for (int i = tid*4; i < 16384; i += 512)
                *(float4*)(hs + i) = __ldcg((const float4*)(hg + i));
            __syncthreads();

            int ml  = tid >> 6;          // 0..1
            int id6 = tid & 63;
            int bb2 = id6 & 31;
            int kh  = id6 >> 5;          // k half
            int m   = blk*2 + ml;
            const float* w = A1_w + (size_t)m*1024 + kh*256;
            const float* hh = hs + kh*256*32;
            float acc = 0.f;
            #pragma unroll 4
            for (int k = 0; k < 256; k += 4){
                float4 v = *(const float4*)(w + k);
                acc += hh[(k+0)*32+bb2]*v.x + hh[(k+1)*32+bb2]*v.y
                     + hh[(k+2)*32+bb2]*v.z + hh[(k+3)*32+bb2]*v.w;
            }
            if (kh == 1) scr[ml*32 + bb2] = acc;
            __syncthreads();
            if (kh == 0) d_hp[bb2*256 + m] = acc + scr[ml*32 + bb2] + A1_b[m];
        }
        grid_bar(DEC_BLOCKS);

        // ---- Phase C: scores[b][s] ----
        {
            int b3   = blk & 31;
            int part = blk >> 5;
            float* hps  = scr;        // 256
            float* scr2 = scr + 256;  // 64
            for (int i = tid; i < 256; i += 128)
                hps[i] = __ldcg(d_hp + b3*256 + i);
            __syncthreads();

            int sl = tid & 63; int mh = tid >> 6;
            int s = part*64 + sl;
            const float* ep  = d_encproj + ((size_t)s*32 + b3)*256 + mh*128;
            const float* aw  = A2_w + mh*128;
            const float* hpp = hps + mh*128;
            float acc = 0.f;
            #pragma unroll 4
            for (int m = 0; m < 128; m += 4){
                float4 e4 = *(const float4*)(ep + m);
                float4 w4 = *(const float4*)(aw + m);
                acc += tanha(hpp[m+0]+e4.x)*w4.x + tanha(hpp[m+1]+e4.y)*w4.y
                     + tanha(hpp[m+2]+e4.z)*w4.z + tanha(hpp[m+3]+e4.w)*w4.w;
            }
            if (mh == 1) scr2[sl] = acc;
            __syncthreads();
            if (mh == 0){
                float sc = acc + scr2[sl] + A2_b[0]
                         + (1.0f - (float)mask[b3*Sq + s]) * (-1e30f);
                d_scoresG[b3*256 + s] = sc;
            }
        }
        grid_bar(DEC_BLOCKS);

        // ---- Phase D: softmax + context (32 active blocks) ----
        if (blk < 32){
            int b4 = blk;
            float* ss  = scr;        // 256
            float* red = scr + 256;  // 8
            for (int i = tid; i < 256; i += 128)
                ss[i] = __ldcg(d_scoresG + b4*256 + i);
            __syncthreads();
            float v = fmaxf(ss[tid], ss[tid+128]);
            #pragma unroll
            for (int o=16;o;o>>=1) v = fmaxf(v, __shfl_xor_sync(0xffffffffu, v, o));
            if ((tid & 31) == 0) red[tid>>5] = v;
            __syncthreads();
            float mx = fmaxf(fmaxf(red[0],red[1]), fmaxf(red[2],red[3]));
            float e0 = expf(ss[tid] - mx), e1 = expf(ss[tid+128] - mx);
            float su = e0 + e1;
            #pragma unroll
            for (int o=16;o;o>>=1) su += __shfl_xor_sync(0xffffffffu, su, o);
            if ((tid & 31) == 0) red[4 + (tid>>5)] = su;
            __syncthreads();
            float inv = 1.0f / (red[4]+red[5]+red[6]+red[7]);
            __syncthreads();
            ss[tid] = e0*inv; ss[tid+128] = e1*inv;
            __syncthreads();

            int d4 = tid*4;
            float4 acc = make_float4(0,0,0,0);
            const float* eb = d_ENC + (size_t)b4*512 + d4;
            #pragma unroll 4
            for (int s = 0; s < 256; s++){
                float a = ss[s];
                float4 ev = *(const float4*)(eb + (size_t)s*32*512);
                acc.x += a*ev.x; acc.y += a*ev.y; acc.z += a*ev.z; acc.w += a*ev.w;
            }
            *(float4*)(d_Z + ((size_t)b4*TQn + t)*1024 + 512 + d4) = acc;
        }
    }
}

// ---------------- host launch ----------------
static void* symaddr(const void* sym){
    void* p = nullptr;
    cudaGetSymbolAddress(&p, sym);
    return p;
}

extern "C" void kernel_launch(void* const* d_in, const int* in_sizes, int n_in,
                              void* d_out, int out_size)
{
    const int*   ctx    = (const int*)  d_in[0];
    const int*   mark   = (const int*)  d_in[1];
    const int*   qid    = (const int*)  d_in[2];
    const int*   mask   = (const int*)  d_in[3];
    const float* embed  = (const float*)d_in[4];
    const float* membed = (const float*)d_in[5];
    const float* Wf_ih  = (const float*)d_in[6];
    const float* Wf_hh  = (const float*)d_in[7];
    const float* bf     = (const float*)d_in[8];
    const float* Wb_ih  = (const float*)d_in[9];
    const float* Wb_hh  = (const float*)d_in[10];
    const float* bb     = (const float*)d_in[11];
    const float* Wd_ih  = (const float*)d_in[12];
    const float* Wd_hh  = (const float*)d_in[13];
    const float* bd     = (const float*)d_in[14];
    const float* A1_w   = (const float*)d_in[15];
    const float* A1_b   = (const float*)d_in[16];
    const float* A2_w   = (const float*)d_in[17];
    const float* A2_b   = (const float*)d_in[18];
    const float* O_w    = (const float*)d_in[19];
    const float* O_b    = (const float*)d_in[20];
    float* out = (float*)d_out;

    float* pX    = (float*)symaddr(d_X);
    float* pxF   = (float*)symaddr(d_xprojF);
    float* pxB   = (float*)symaddr(d_xprojB);
    float* pENC  = (float*)symaddr(d_ENC);
    float* pproj = (float*)symaddr(d_encproj);
    float* pZ    = (float*)symaddr(d_Z);

    static bool attr_done = false;
    if (!attr_done){
        cudaFuncSetAttribute(k_enc_persist, cudaFuncAttributeMaxDynamicSharedMemorySize, 49152);
        cudaFuncSetAttribute(k_dec_persist, cudaFuncAttributeMaxDynamicSharedMemorySize, 122880);
        attr_done = true;
    }

    // 1. embeddings + Wcomb
    k_setup<<<2048, 256>>>(ctx, mark, qid, embed, membed, Wd_ih, Wd_hh);

    // 2. x-projections for both directions (bias folded in)
    k_gemm<<<dim3(1024/GBN, (Sq*Bq)/GBM), 256>>>(pX, 256, Wf_ih, 256, bf, pxF, 1024, Sq*Bq, 1024, 256);
    k_gemm<<<dim3(1024/GBN, (Sq*Bq)/GBM), 256>>>(pX, 256, Wb_ih, 256, bb, pxB, 1024, Sq*Bq, 1024, 256);

    // 3. persistent encoder recurrence (both directions, 256 steps, grid barriers)
    k_enc_persist<<<ENC_BLOCKS, 128, 49152>>>(Wf_hh, Wb_hh);

    // 4. encoder-side attention projection
    k_gemm<<<dim3(256/GBN, (Sq*Bq)/GBM), 256>>>(pENC, 512, A1_w + 512, 1024, nullptr, pproj, 256, Sq*Bq, 256, 512);

    // 5. persistent decoder (LSTM + attention fused, 31 steps)
    k_dec_persist<<<DEC_BLOCKS, 128, 122880>>>(Wd_ih, bd, A1_w, A1_b, A2_w, A2_b, mask);

    // 6. big output projection straight into d_out ([b*31+t] rows == [B,T-1,V])
    k_gemm<<<dim3(Vq/GBN, (TQn*Bq + GBM - 1)/GBM), 256>>>(pZ, 1024, O_w, 1024, O_b, out, Vq, TQn*Bq, Vq, 1024);

    (void)in_sizes; (void)n_in; (void)out_size;
}

// round 8
// speedup vs baseline: 3.0719x; 1.1985x over previous
#include <cuda_runtime.h>
#include <cuda_bf16.h>
#include <cstdint>
#include <math.h>

typedef unsigned int       u32;
typedef unsigned long long u64;

#define Bq  32
#define Sq  256
#define Tq  32
#define TQn 31
#define Vq  32000
#define Eq  128
#define Hq  256
#define HDq 512

// ---------------- scratch (device globals; no allocation) ----------------
__device__ float d_X[Sq*Bq*2*Eq];
__device__ float d_xprojF[Sq*Bq*4*Hq];
__device__ float d_xprojB[Sq*Bq*4*Hq];
__device__ float d_ENC[Sq*Bq*2*Hq];
__device__ float d_encproj[Sq*Bq*Hq];
__device__ float d_hT[2][2][Hq*Bq];
__device__ float d_cT[2][Hq*Bq];
__device__ float d_hdT[2][HDq*Bq];
__device__ float d_qxT[TQn*Eq*Bq];
__device__ float d_Wcomb[4*HDq*HDq];
__device__ float d_Z[TQn*Bq*2*HDq];        // [(b*31+t), 1024]
__device__ float d_hp[Bq*Hq];
__device__ float d_scoresG[Bq*Sq];

// bf16 split operands for the big projection (plain row-major)
__device__ __align__(16) __nv_bfloat16 d_Bhi[(size_t)Vq*1024];   // [32000][1024]
__device__ __align__(16) __nv_bfloat16 d_Blo[(size_t)Vq*1024];
__device__ __align__(16) __nv_bfloat16 d_Ahi[1024*1024];         // [1024][1024], rows >=992 zero
__device__ __align__(16) __nv_bfloat16 d_Alo[1024*1024];

__device__ unsigned g_bar_cnt = 0;
__device__ unsigned g_bar_gen = 0;

__device__ __forceinline__ float sigm(float x){ return 1.0f/(1.0f+expf(-x)); }
__device__ __forceinline__ float tanh_(float x){ return 1.0f - 2.0f/(expf(2.0f*x)+1.0f); }
__device__ __forceinline__ float tanha(float x){ float y; asm("tanh.approx.f32 %0, %1;" : "=f"(y) : "f"(x)); return y; }

__device__ __forceinline__ void grid_bar(unsigned nb){
    __syncthreads();
    if (threadIdx.x == 0){
        unsigned gen = *((volatile unsigned*)&g_bar_gen);
        __threadfence();
        unsigned ticket = atomicAdd(&g_bar_cnt, 1);
        if (ticket == nb - 1){
            g_bar_cnt = 0;
            __threadfence();
            atomicAdd(&g_bar_gen, 1);
        } else {
            while (*((volatile unsigned*)&g_bar_gen) == gen) {}
        }
    }
    __syncthreads();
}

// ---------------- setup: embeddings, Wcomb ----------------
__global__ void k_setup(const int* __restrict__ ctx, const int* __restrict__ mark,
                        const int* __restrict__ qid,
                        const float* __restrict__ embed, const float* __restrict__ membed,
                        const float* __restrict__ Wd_ih, const float* __restrict__ Wd_hh)
{
    const int NX = Sq*Bq*256;
    const int NQ = TQn*Eq*Bq;
    const int NW = 4*HDq*HDq;
    const int total = NX + NQ + NW;
    for (int idx = blockIdx.x*blockDim.x + threadIdx.x; idx < total; idx += gridDim.x*blockDim.x){
        if (idx < NX){
            int row = idx >> 8; int k = idx & 255;
            int s = row >> 5, b = row & 31;
            float v;
            if (k < Eq) v = embed[(size_t)ctx[b*Sq+s]*Eq + k];
            else        v = membed[(size_t)mark[b*Sq+s]*Eq + (k-Eq)];
            d_X[idx] = v;
        } else if (idx < NX+NQ){
            int i = idx - NX;
            int t = i/(Eq*Bq); int r = i%(Eq*Bq); int k = r >> 5; int b = r & 31;
            d_qxT[i] = embed[(size_t)qid[b*Tq+t]*Eq + k];
        } else {
            int i = idx - NX - NQ; int j = i >> 9; int k = i & 511;
            d_Wcomb[i] = Wd_ih[(size_t)j*640 + 128 + k] + Wd_hh[(size_t)j*512 + k];
        }
    }
}

// ---------------- convert O_w -> hi/lo bf16 row-major ----------------
__global__ void k_cvtB(const float* __restrict__ W)
{
    const int total = Vq * 512;   // bf16x2 pairs
    for (int idx = blockIdx.x*blockDim.x + threadIdx.x; idx < total; idx += gridDim.x*blockDim.x){
        int n = idx >> 9; int kp = idx & 511; int k = kp << 1;
        float v0 = W[(size_t)n*1024 + k];
        float v1 = W[(size_t)n*1024 + k + 1];
        __nv_bfloat16 h0 = __float2bfloat16(v0), h1 = __float2bfloat16(v1);
        __nv_bfloat16 l0 = __float2bfloat16(v0 - __bfloat162float(h0));
        __nv_bfloat16 l1 = __float2bfloat16(v1 - __bfloat162float(h1));
        *(__nv_bfloat162*)(d_Bhi + (size_t)n*1024 + k) = __halves2bfloat162(h0, h1);
        *(__nv_bfloat162*)(d_Blo + (size_t)n*1024 + k) = __halves2bfloat162(l0, l1);
    }
}

// ---------------- convert Z -> hi/lo bf16 row-major (pad to 1024 rows) ----------------
__global__ void k_cvtA()
{
    const int total = 1024 * 512;
    for (int idx = blockIdx.x*blockDim.x + threadIdx.x; idx < total; idx += gridDim.x*blockDim.x){
        int m = idx >> 9; int kp = idx & 511; int k = kp << 1;
        float v0 = 0.f, v1 = 0.f;
        if (m < TQn*Bq){
            v0 = d_Z[(size_t)m*1024 + k];
            v1 = d_Z[(size_t)m*1024 + k + 1];
        }
        __nv_bfloat16 h0 = __float2bfloat16(v0), h1 = __float2bfloat16(v1);
        __nv_bfloat16 l0 = __float2bfloat16(v0 - __bfloat162float(h0));
        __nv_bfloat16 l1 = __float2bfloat16(v1 - __bfloat162float(h1));
        *(__nv_bfloat162*)(d_Ahi + (size_t)m*1024 + k) = __halves2bfloat162(h0, h1);
        *(__nv_bfloat162*)(d_Alo + (size_t)m*1024 + k) = __halves2bfloat162(l0, l1);
    }
}

// ---------------- mma.sync bf16 output projection ----------------
// C[992,32000] = Z * O_w^T + O_b, 3-term bf16 split, f32 accumulate.
// 256 threads (8 warps, 4x2), CTA tile 128x128, K chunks of 32.
// grid (8 Mtiles, 250 Ntiles) — x fastest so CTAs sharing a B tile co-schedule.
#define ASTR 40   // smem row stride in bf16 elements (80B -> conflict-free frag loads)
__device__ __forceinline__ void mma_bf16(float* c, u32 a0, u32 a1, u32 a2, u32 a3, u32 b0, u32 b1){
    asm volatile(
        "mma.sync.aligned.m16n8k16.row.col.f32.bf16.bf16.f32 "
        "{%0,%1,%2,%3}, {%4,%5,%6,%7}, {%8,%9}, {%0,%1,%2,%3};"
        : "+f"(c[0]), "+f"(c[1]), "+f"(c[2]), "+f"(c[3])
        : "r"(a0), "r"(a1), "r"(a2), "r"(a3), "r"(b0), "r"(b1));
}
__global__ void __launch_bounds__(256)
k_gemm_mma(const float* __restrict__ O_b, float* __restrict__ out)
{
    __shared__ __nv_bfloat16 sA[2][128*ASTR];   // [hi/lo]
    __shared__ __nv_bfloat16 sB[2][128*ASTR];
    int tid = threadIdx.x;
    int warp = tid >> 5, lane = tid & 31;
    int bm = blockIdx.x, bn = blockIdx.y;
    int wm = warp >> 1, wn = warp & 1;          // 4 x 2 warp grid
    int r = lane >> 2, cp = (lane & 3) << 1;    // fragment row / col-pair

    float acc[2][8][4];
    #pragma unroll
    for (int i=0;i<2;i++)
        #pragma unroll
        for (int j=0;j<8;j++){ acc[i][j][0]=0.f; acc[i][j][1]=0.f; acc[i][j][2]=0.f; acc[i][j][3]=0.f; }

    for (int kc = 0; kc < 1024; kc += 32){
        // load tiles: 4 arrays x 512 uint4
        for (int i = tid; i < 512; i += 256){
            int row = i >> 2, seg = i & 3;
            size_t ga = ((size_t)(bm*128+row))*1024 + kc;
            size_t gb = ((size_t)(bn*128+row))*1024 + kc;
            *(uint4*)&sA[0][row*ASTR + seg*8] = ((const uint4*)(d_Ahi + ga))[seg];
            *(uint4*)&sA[1][row*ASTR + seg*8] = ((const uint4*)(d_Alo + ga))[seg];
            *(uint4*)&sB[0][row*ASTR + seg*8] = ((const uint4*)(d_Bhi + gb))[seg];
            *(uint4*)&sB[1][row*ASTR + seg*8] = ((const uint4*)(d_Blo + gb))[seg];
        }
        __syncthreads();

        #pragma unroll
        for (int ks = 0; ks < 2; ks++){
            int k0 = ks*16;
            u32 af[2][2][4];
            #pragma unroll
            for (int t = 0; t < 2; t++)
                #pragma unroll
                for (int mi = 0; mi < 2; mi++){
                    int ar = wm*32 + mi*16 + r;
                    af[t][mi][0] = *(const u32*)&sA[t][(ar  )*ASTR + k0 + cp    ];
                    af[t][mi][1] = *(const u32*)&sA[t][(ar+8)*ASTR + k0 + cp    ];
                    af[t][mi][2] = *(const u32*)&sA[t][(ar  )*ASTR + k0 + cp + 8];
                    af[t][mi][3] = *(const u32*)&sA[t][(ar+8)*ASTR + k0 + cp + 8];
                }
            u32 bf[2][8][2];
            #pragma unroll
            for (int t = 0; t < 2; t++)
                #pragma unroll
                for (int ni = 0; ni < 8; ni++){
                    int br = wn*64 + ni*8 + r;
                    bf[t][ni][0] = *(const u32*)&sB[t][br*ASTR + k0 + cp    ];
                    bf[t][ni][1] = *(const u32*)&sB[t][br*ASTR + k0 + cp + 8];
                }
            #pragma unroll
            for (int mi = 0; mi < 2; mi++)
                #pragma unroll
                for (int ni = 0; ni < 8; ni++){
                    float* c = acc[mi][ni];
                    mma_bf16(c, af[0][mi][0], af[0][mi][1], af[0][mi][2], af[0][mi][3],
                             bf[0][ni][0], bf[0][ni][1]);                       // hi*hi
                    mma_bf16(c, af[0][mi][0], af[0][mi][1], af[0][mi][2], af[0][mi][3],
                             bf[1][ni][0], bf[1][ni][1]);                       // hi*lo
                    mma_bf16(c, af[1][mi][0], af[1][mi][1], af[1][mi][2], af[1][mi][3],
                             bf[0][ni][0], bf[0][ni][1]);                       // lo*hi
                }
        }
        __syncthreads();
    }

    // epilogue: c0,c1 -> (row, cp..cp+1); c2,c3 -> (row+8, cp..cp+1)
    #pragma unroll
    for (int mi = 0; mi < 2; mi++){
        #pragma unroll
        for (int ni = 0; ni < 8; ni++){
            int n = bn*128 + wn*64 + ni*8 + cp;
            float2 bias = *(const float2*)(O_b + n);
            int m0 = bm*128 + wm*32 + mi*16 + r;
            if (m0 < TQn*Bq){
                float2 v; v.x = acc[mi][ni][0] + bias.x; v.y = acc[mi][ni][1] + bias.y;
                *(float2*)(out + (size_t)m0*Vq + n) = v;
            }
            int m1 = m0 + 8;
            if (m1 < TQn*Bq){
                float2 v; v.x = acc[mi][ni][2] + bias.x; v.y = acc[mi][ni][3] + bias.y;
                *(float2*)(out + (size_t)m1*Vq + n) = v;
            }
        }
    }
}

// ---------------- generic fp32 GEMM: C[M,N] = A[M,K] * B[N,K]^T + bias ----------------
#define GBM 128
#define GBN 64
#define GBK 16
__global__ void __launch_bounds__(256)
k_gemm(const float* __restrict__ A, int lda,
       const float* __restrict__ Bw, int ldb,
       const float* __restrict__ bias,
       float* __restrict__ C, int ldc,
       int M, int N, int K)
{
    __shared__ float As[GBK][GBM+4];
    __shared__ float Bs[GBK][GBN+4];
    int tid = threadIdx.x;
    int tx = tid & 15, ty = tid >> 4;
    int m0 = blockIdx.y * GBM, n0 = blockIdx.x * GBN;

    float acc[8][4];
    #pragma unroll
    for (int i=0;i<8;i++){ acc[i][0]=0.f;acc[i][1]=0.f;acc[i][2]=0.f;acc[i][3]=0.f; }

    int arow = tid >> 1;
    int ak   = (tid & 1) * 8;
    int brow = tid >> 2;
    int bk   = (tid & 3) * 4;

    for (int k0 = 0; k0 < K; k0 += GBK){
        {
            int gm = m0 + arow;
            float4 v0, v1;
            if (gm < M){
                const float* src = A + (size_t)gm*lda + k0 + ak;
                v0 = *(const float4*)src;
                v1 = *(const float4*)(src+4);
            } else {
                v0 = make_float4(0,0,0,0); v1 = v0;
            }
            As[ak+0][arow]=v0.x; As[ak+1][arow]=v0.y; As[ak+2][arow]=v0.z; As[ak+3][arow]=v0.w;
            As[ak+4][arow]=v1.x; As[ak+5][arow]=v1.y; As[ak+6][arow]=v1.z; As[ak+7][arow]=v1.w;
        }
        {
            int gn = n0 + brow;
            float4 v = *(const float4*)(Bw + (size_t)gn*ldb + k0 + bk);
            Bs[bk+0][brow]=v.x; Bs[bk+1][brow]=v.y; Bs[bk+2][brow]=v.z; Bs[bk+3][brow]=v.w;
        }
        __syncthreads();
        #pragma unroll
        for (int kk = 0; kk < GBK; kk++){
            float4 b4 = *(const float4*)&Bs[kk][tx*4];
            float4 a0 = *(const float4*)&As[kk][ty*8];
            float4 a1 = *(const float4*)&As[kk][ty*8+4];
            float av[8] = {a0.x,a0.y,a0.z,a0.w,a1.x,a1.y,a1.z,a1.w};
            float bv[4] = {b4.x,b4.y,b4.z,b4.w};
            #pragma unroll
            for (int i=0;i<8;i++){
                #pragma unroll
                for (int j=0;j<4;j++) acc[i][j] = fmaf(av[i], bv[j], acc[i][j]);
            }
        }
        __syncthreads();
    }

    float4 bb = make_float4(0,0,0,0);
    if (bias) bb = *(const float4*)(bias + n0 + tx*4);
    #pragma unroll
    for (int i=0;i<8;i++){
        int gm = m0 + ty*8 + i;
        if (gm < M){
            float4 o;
            o.x = acc[i][0]+bb.x; o.y = acc[i][1]+bb.y;
            o.z = acc[i][2]+bb.z; o.w = acc[i][3]+bb.w;
            *(float4*)(C + (size_t)gm*ldc + n0 + tx*4) = o;
        }
    }
}

// ---------------- persistent encoder: 128 blocks x 128 threads ----------------
#define ENC_BLOCKS 128
__global__ void __launch_bounds__(128)
k_enc_persist(const float* __restrict__ Wf_hh, const float* __restrict__ Wb_hh)
{
    extern __shared__ float sm[];
    float* ws = sm;
    float* hs = sm + 4096;

    int blk  = blockIdx.x;
    int dir  = blk >> 6;
    int ublk = blk & 63;
    int tid  = threadIdx.x;
    int lj   = tid >> 5;
    int b    = tid & 31;
    int jj   = ublk*4 + lj;
    const float* __restrict__ Whh = dir ? Wb_hh : Wf_hh;
    const float* __restrict__ xp  = dir ? d_xprojB : d_xprojF;

    for (int f = tid*4; f < 4096; f += 512){
        int l = f >> 10; int g = (f >> 8) & 3; int k = f & 255;
        int row = g*256 + ublk*4 + l;
        *(float4*)(ws + f) = *(const float4*)(Whh + (size_t)row*256 + k);
    }
    d_hT[dir][0][jj*32 + b] = 0.0f;
    float c = 0.0f;

    const float* w0 = ws + (lj*4+0)*256;
    const float* w1 = ws + (lj*4+1)*256;
    const float* w2 = ws + (lj*4+2)*256;
    const float* w3 = ws + (lj*4+3)*256;

    for (int t = 0; t < Sq; t++){
        grid_bar(ENC_BLOCKS);
        const float* hg = d_hT[dir][t & 1];
        for (int i = tid*4; i < 8192; i += 512)
            *(float4*)(hs + i) = __ldcg((const float4*)(hg + i));
        __syncthreads();

        int s = dir ? (255 - t) : t;
        const float* base = xp + (size_t)(s*32 + b)*1024 + jj;
        float a0 = base[0], a1 = base[256], a2 = base[512], a3 = base[768];
        #pragma unroll 4
        for (int k = 0; k < 256; k += 4){
            float4 v0 = *(const float4*)(w0 + k);
            float4 v1 = *(const float4*)(w1 + k);
            float4 v2 = *(const float4*)(w2 + k);
            float4 v3 = *(const float4*)(w3 + k);
            float h0 = hs[(k+0)*32+b], h1 = hs[(k+1)*32+b];
            float h2 = hs[(k+2)*32+b], h3 = hs[(k+3)*32+b];
            a0 += h0*v0.x + h1*v0.y + h2*v0.z + h3*v0.w;
            a1 += h0*v1.x + h1*v1.y + h2*v1.z + h3*v1.w;
            a2 += h0*v2.x + h1*v2.y + h2*v2.z + h3*v2.w;
            a3 += h0*v3.x + h1*v3.y + h2*v3.z + h3*v3.w;
        }
        float cn = sigm(a1)*c + sigm(a0)*tanh_(a2);
        float hn = sigm(a3)*tanh_(cn);
        c = cn;
        d_hT[dir][(t&1)^1][jj*32+b] = hn;
        d_ENC[(size_t)(s*32+b)*512 + dir*256 + jj] = hn;
    }
    d_cT[dir][jj*32+b] = c;
}

// ---------------- persistent decoder: 128 blocks x 128 threads ----------------
#define DEC_BLOCKS 128
__global__ void __launch_bounds__(128)
k_dec_persist(const float* __restrict__ Wd_ih, const float* __restrict__ bd,
              const float* __restrict__ A1_w,  const float* __restrict__ A1_b,
              const float* __restrict__ A2_w,  const float* __restrict__ A2_b,
              const int*   __restrict__ mask)
{
    extern __shared__ float sm[];
    float* wd  = sm;
    float* hs  = sm + 10240;
    float* scr = sm + 10240 + 16384;

    int blk = blockIdx.x;
    int tid = threadIdx.x;
    int lj  = tid >> 5;
    int b   = tid & 31;
    int jj  = blk*4 + lj;

    for (int f = tid*4; f < 10240; f += 512){
        int l = f / 2560; int r = f % 2560; int g = r / 640; int k = r % 640;
        int row = g*512 + blk*4 + l;
        float4 v;
        if (k < 128) v = *(const float4*)(Wd_ih  + (size_t)row*640 + k);
        else         v = *(const float4*)(d_Wcomb + (size_t)row*512 + (k-128));
        *(float4*)(wd + f) = v;
    }

    float c;
    {
        float hv;
        if (jj < Hq){ hv = d_hT[0][0][jj*32+b];       c = d_cT[0][jj*32+b]; }
        else        { hv = d_hT[1][0][(jj-Hq)*32+b];  c = d_cT[1][(jj-Hq)*32+b]; }
        d_hdT[0][jj*32+b] = hv;
    }

    const float* w0 = wd + (lj*4+0)*640;
    const float* w1 = wd + (lj*4+1)*640;
    const float* w2 = wd + (lj*4+2)*640;
    const float* w3 = wd + (lj*4+3)*640;
    float bd0 = bd[jj], bd1 = bd[512+jj], bd2 = bd[1024+jj], bd3 = bd[1536+jj];

    for (int t = 0; t < TQn; t++){
        grid_bar(DEC_BLOCKS);
        {
            const float* hg = d_hdT[t & 1];
            for (int i = tid*4; i < 16384; i += 512)
                *(float4*)(hs + i) = __ldcg((const float4*)(hg + i));
            const float* qg = d_qxT + (size_t)t*Eq*Bq;
            for (int i = tid*4; i < 4096; i += 512)
                *(float4*)(scr + i) = *(const float4*)(qg + i);
        }
        __syncthreads();

        {
            float a0 = bd0, a1 = bd1, a2 = bd2, a3 = bd3;
            #pragma unroll 4
            for (int k = 0; k < 128; k += 4){
                float4 v0 = *(const float4*)(w0 + k);
                float4 v1 = *(const float4*)(w1 + k);
                float4 v2 = *(const float4*)(w2 + k);
                float4 v3 = *(const float4*)(w3 + k);
                float x0 = scr[(k+0)*32+b], x1 = scr[(k+1)*32+b];
                float x2 = scr[(k+2)*32+b], x3 = scr[(k+3)*32+b];
                a0 += x0*v0.x + x1*v0.y + x2*v0.z + x3*v0.w;
                a1 += x0*v1.x + x1*v1.y + x2*v1.z + x3*v1.w;
                a2 += x0*v2.x + x1*v2.y + x2*v2.z + x3*v2.w;
                a3 += x0*v3.x + x1*v3.y + x2*v3.z + x3*v3.w;
            }
            #pragma unroll 4
            for (int k = 0; k < 512; k += 4){
                float4 v0 = *(const float4*)(w0 + 128 + k);
                float4 v1 = *(const float4*)(w1 + 128 + k);
                float4 v2 = *(const float4*)(w2 + 128 + k);
                float4 v3 = *(const float4*)(w3 + 128 + k);
                float h0 = hs[(k+0)*32+b], h1 = hs[(k+1)*32+b];
                float h2 = hs[(k+2)*32+b], h3 = hs[(k+3)*32+b];
                a0 += h0*v0.x + h1*v0.y + h2*v0.z + h3*v0.w;
                a1 += h0*v1.x + h1*v1.y + h2*v1.z + h3*v1.w;
                a2 += h0*v2.x + h1*v2.y + h2*v2.z + h3*v2.w;
                a3 += h0*v3.x + h1*v3.y + h2*v3.z + h3*v3.w;
            }
            float cn = sigm(a1)*c + sigm(a0)*tanh_(a2);
            float hn = sigm(a3)*tanh_(cn);
            c = cn;
            d_hdT[(t&1)^1][jj*32+b] = hn;
            d_Z[((size_t)b*TQn + t)*1024 + jj] = hn;
        }
        grid_bar(DEC_BLOCKS);

        {
            const float* hg = d_hdT[(t&1)^1];
            for (int i = tid*4; i < 16384; i += 512)
                *(float4*)(hs + i) = __ldcg((const float4*)(hg + i));
            __syncthreads();

            int ml  = tid >> 6;
            int id6 = tid & 63;
            int bb2 = id6 & 31;
            int kh  = id6 >> 5;
            int m   = blk*2 + ml;
            const float* w = A1_w + (size_t)m*1024 + kh*256;
            const float* hh = hs + kh*256*32;
            float acc = 0.f;
            #pragma unroll 4
            for (int k = 0; k < 256; k += 4){
                float4 v = *(const float4*)(w + k);
                acc += hh[(k+0)*32+bb2]*v.x + hh[(k+1)*32+bb2]*v.y
                     + hh[(k+2)*32+bb2]*v.z + hh[(k+3)*32+bb2]*v.w;
            }
            if (kh == 1) scr[ml*32 + bb2] = acc;
            __syncthreads();
            if (kh == 0) d_hp[bb2*256 + m] = acc + scr[ml*32 + bb2] + A1_b[m];
        }
        grid_bar(DEC_BLOCKS);

        {
            int b3   = blk & 31;
            int part = blk >> 5;
            float* hps  = scr;
            float* scr2 = scr + 256;
            for (int i = tid; i < 256; i += 128)
                hps[i] = __ldcg(d_hp + b3*256 + i);
            __syncthreads();

            int sl = tid & 63; int mh = tid >> 6;
            int s = part*64 + sl;
            const float* ep  = d_encproj + ((size_t)s*32 + b3)*256 + mh*128;
            const float* aw  = A2_w + mh*128;
            const float* hpp = hps + mh*128;
            float acc = 0.f;
            #pragma unroll 4
            for (int m = 0; m < 128; m += 4){
                float4 e4 = *(const float4*)(ep + m);
                float4 w4 = *(const float4*)(aw + m);
                acc += tanha(hpp[m+0]+e4.x)*w4.x + tanha(hpp[m+1]+e4.y)*w4.y
                     + tanha(hpp[m+2]+e4.z)*w4.z + tanha(hpp[m+3]+e4.w)*w4.w;
            }
            if (mh == 1) scr2[sl] = acc;
            __syncthreads();
            if (mh == 0){
                float sc = acc + scr2[sl] + A2_b[0]
                         + (1.0f - (float)mask[b3*Sq + s]) * (-1e30f);
                d_scoresG[b3*256 + s] = sc;
            }
        }
        grid_bar(DEC_BLOCKS);

        if (blk < 32){
            int b4 = blk;
            float* ss  = scr;
            float* red = scr + 256;
            for (int i = tid; i < 256; i += 128)
                ss[i] = __ldcg(d_scoresG + b4*256 + i);
            __syncthreads();
            float v = fmaxf(ss[tid], ss[tid+128]);
            #pragma unroll
            for (int o=16;o;o>>=1) v = fmaxf(v, __shfl_xor_sync(0xffffffffu, v, o));
            if ((tid & 31) == 0) red[tid>>5] = v;
            __syncthreads();
            float mx = fmaxf(fmaxf(red[0],red[1]), fmaxf(red[2],red[3]));
            float e0 = expf(ss[tid] - mx), e1 = expf(ss[tid+128] - mx);
            float su = e0 + e1;
            #pragma unroll
            for (int o=16;o;o>>=1) su += __shfl_xor_sync(0xffffffffu, su, o);
            if ((tid & 31) == 0) red[4 + (tid>>5)] = su;
            __syncthreads();
            float inv = 1.0f / (red[4]+red[5]+red[6]+red[7]);
            __syncthreads();
            ss[tid] = e0*inv; ss[tid+128] = e1*inv;
            __syncthreads();

            int d4 = tid*4;
            float4 acc = make_float4(0,0,0,0);
            const float* eb = d_ENC + (size_t)b4*512 + d4;
            #pragma unroll 4
            for (int s = 0; s < 256; s++){
                float a = ss[s];
                float4 ev = *(const float4*)(eb + (size_t)s*32*512);
                acc.x += a*ev.x; acc.y += a*ev.y; acc.z += a*ev.z; acc.w += a*ev.w;
            }
            *(float4*)(d_Z + ((size_t)b4*TQn + t)*1024 + 512 + d4) = acc;
        }
    }
}

// ---------------- host launch ----------------
static void* symaddr(const void* sym){
    void* p = nullptr;
    cudaGetSymbolAddress(&p, sym);
    return p;
}

extern "C" void kernel_launch(void* const* d_in, const int* in_sizes, int n_in,
                              void* d_out, int out_size)
{
    const int*   ctx    = (const int*)  d_in[0];
    const int*   mark   = (const int*)  d_in[1];
    const int*   qid    = (const int*)  d_in[2];
    const int*   mask   = (const int*)  d_in[3];
    const float* embed  = (const float*)d_in[4];
    const float* membed = (const float*)d_in[5];
    const float* Wf_ih  = (const float*)d_in[6];
    const float* Wf_hh  = (const float*)d_in[7];
    const float* bf     = (const float*)d_in[8];
    const float* Wb_ih  = (const float*)d_in[9];
    const float* Wb_hh  = (const float*)d_in[10];
    const float* bb     = (const float*)d_in[11];
    const float* Wd_ih  = (const float*)d_in[12];
    const float* Wd_hh  = (const float*)d_in[13];
    const float* bd     = (const float*)d_in[14];
    const float* A1_w   = (const float*)d_in[15];
    const float* A1_b   = (const float*)d_in[16];
    const float* A2_w   = (const float*)d_in[17];
    const float* A2_b   = (const float*)d_in[18];
    const float* O_w    = (const float*)d_in[19];
    const float* O_b    = (const float*)d_in[20];
    float* out = (float*)d_out;

    float* pX    = (float*)symaddr(d_X);
    float* pxF   = (float*)symaddr(d_xprojF);
    float* pxB   = (float*)symaddr(d_xprojB);
    float* pENC  = (float*)symaddr(d_ENC);
    float* pproj = (float*)symaddr(d_encproj);

    cudaFuncSetAttribute(k_enc_persist, cudaFuncAttributeMaxDynamicSharedMemorySize, 49152);
    cudaFuncSetAttribute(k_dec_persist, cudaFuncAttributeMaxDynamicSharedMemorySize, 122880);

    // 1. embeddings + Wcomb; O_w split conversion (independent of everything else)
    k_setup<<<2048, 256>>>(ctx, mark, qid, embed, membed, Wd_ih, Wd_hh);
    k_cvtB<<<4096, 256>>>(O_w);

    // 2. x-projections (bias folded in)
    k_gemm<<<dim3(1024/GBN, (Sq*Bq)/GBM), 256>>>(pX, 256, Wf_ih, 256, bf, pxF, 1024, Sq*Bq, 1024, 256);
    k_gemm<<<dim3(1024/GBN, (Sq*Bq)/GBM), 256>>>(pX, 256, Wb_ih, 256, bb, pxB, 1024, Sq*Bq, 1024, 256);

    // 3. persistent encoder recurrence
    k_enc_persist<<<ENC_BLOCKS, 128, 49152>>>(Wf_hh, Wb_hh);

    // 4. encoder-side attention projection
    k_gemm<<<dim3(256/GBN, (Sq*Bq)/GBM), 256>>>(pENC, 512, A1_w + 512, 1024, nullptr, pproj, 256, Sq*Bq, 256, 512);

    // 5. persistent decoder (LSTM + attention fused)
    k_dec_persist<<<DEC_BLOCKS, 128, 122880>>>(Wd_ih, bd, A1_w, A1_b, A2_w, A2_b, mask);

    // 6. Z -> bf16 hi/lo, then mma.sync output projection into d_out
    k_cvtA<<<512, 256>>>();
    k_gemm_mma<<<dim3(8, 250), 256>>>(O_b, out);

    (void)in_sizes; (void)n_in; (void)out_size;
}